// round 4
// baseline (speedup 1.0000x reference)
#include <cuda_runtime.h>
#include <cuda_bf16.h>

#define FEAT 384
#define FEAT4 (FEAT / 4)   // 96 float4 per row
#define ALPHA 0.2f

__global__ void zero_out_kernel(float* out) {
    if (threadIdx.x == 0 && blockIdx.x == 0) out[0] = 0.0f;
}

__global__ __launch_bounds__(256) void triplet_kernel(
    const float4* __restrict__ anchor,
    const float4* __restrict__ positive,
    const float4* __restrict__ negative,
    const float*  __restrict__ W,
    float* __restrict__ out,
    int B)
{
    __shared__ float expw[FEAT];
    __shared__ float block_sum;

    for (int i = threadIdx.x; i < FEAT; i += blockDim.x)
        expw[i] = expf(W[i]);
    if (threadIdx.x == 0) block_sum = 0.0f;
    __syncthreads();

    const int lane  = threadIdx.x & 31;
    const int warp  = threadIdx.x >> 5;
    const int wpb   = blockDim.x >> 5;
    const int gwarp = blockIdx.x * wpb + warp;
    const int nwarp = gridDim.x * wpb;

    // Register-resident exp(W): lane's 3 float4, reused every row.
    float4 wv[3];
    #pragma unroll
    for (int j = 0; j < 3; j++)
        wv[j] = *reinterpret_cast<const float4*>(&expw[(j * 32 + lane) * 4]);

    float acc = 0.0f;   // meaningful on lane 0

    // Two rows per warp iteration: independent shfl trees interleave.
    for (int base = gwarp * 2; base < B; base += nwarp * 2) {
        const float4* ar0 = anchor   + (long long)base * FEAT4;
        const float4* pr0 = positive + (long long)base * FEAT4;
        const float4* nr0 = negative + (long long)base * FEAT4;
        const float4* ar1 = ar0 + FEAT4;
        const float4* pr1 = pr0 + FEAT4;
        const float4* nr1 = nr0 + FEAT4;

        float d0 = 0.0f, d1 = 0.0f;
        #pragma unroll
        for (int j = 0; j < 3; j++) {
            const int idx = j * 32 + lane;
            const float4 av0 = __ldg(&ar0[idx]);
            const float4 pv0 = __ldg(&pr0[idx]);
            const float4 nv0 = __ldg(&nr0[idx]);
            const float4 av1 = __ldg(&ar1[idx]);
            const float4 pv1 = __ldg(&pr1[idx]);
            const float4 nv1 = __ldg(&nr1[idx]);

            float dp, dn;
            dp = av0.x - pv0.x; dn = av0.x - nv0.x; d0 += wv[j].x * (dp * dp - dn * dn);
            dp = av0.y - pv0.y; dn = av0.y - nv0.y; d0 += wv[j].y * (dp * dp - dn * dn);
            dp = av0.z - pv0.z; dn = av0.z - nv0.z; d0 += wv[j].z * (dp * dp - dn * dn);
            dp = av0.w - pv0.w; dn = av0.w - nv0.w; d0 += wv[j].w * (dp * dp - dn * dn);

            dp = av1.x - pv1.x; dn = av1.x - nv1.x; d1 += wv[j].x * (dp * dp - dn * dn);
            dp = av1.y - pv1.y; dn = av1.y - nv1.y; d1 += wv[j].y * (dp * dp - dn * dn);
            dp = av1.z - pv1.z; dn = av1.z - nv1.z; d1 += wv[j].z * (dp * dp - dn * dn);
            dp = av1.w - pv1.w; dn = av1.w - nv1.w; d1 += wv[j].w * (dp * dp - dn * dn);
        }

        // Two independent butterfly reductions, interleaved.
        #pragma unroll
        for (int off = 16; off > 0; off >>= 1) {
            d0 += __shfl_xor_sync(0xFFFFFFFFu, d0, off);
            d1 += __shfl_xor_sync(0xFFFFFFFFu, d1, off);
        }

        if (lane == 0)
            acc += fmaxf(d0 + ALPHA, 0.0f) + fmaxf(d1 + ALPHA, 0.0f);
    }

    if (lane == 0)
        atomicAdd(&block_sum, acc);
    __syncthreads();

    if (threadIdx.x == 0)
        atomicAdd(out, block_sum * (1.0f / (float)B));
}

extern "C" void kernel_launch(void* const* d_in, const int* in_sizes, int n_in,
                              void* d_out, int out_size) {
    const float4* anchor   = (const float4*)d_in[0];
    const float4* positive = (const float4*)d_in[1];
    const float4* negative = (const float4*)d_in[2];
    const float*  W        = (const float*)d_in[3];
    float* out = (float*)d_out;

    const int B = in_sizes[0] / FEAT;   // 131072

    zero_out_kernel<<<1, 32>>>(out);

    const int threads = 256;
    const int blocks  = 740;            // 148 SMs * 5 resident blocks @48 regs -> one full wave
    triplet_kernel<<<blocks, threads>>>(anchor, positive, negative, W, out, B);
}

// round 5
// speedup vs baseline: 1.1205x; 1.1205x over previous
#include <cuda_runtime.h>
#include <cuda_bf16.h>

#define FEAT 384
#define FEAT4 (FEAT / 4)   // 96 float4 per row
#define ALPHA 0.2f

__global__ void zero_out_kernel(float* out) {
    if (threadIdx.x == 0 && blockIdx.x == 0) out[0] = 0.0f;
}

__global__ __launch_bounds__(256, 5) void triplet_kernel(
    const float4* __restrict__ anchor,
    const float4* __restrict__ positive,
    const float4* __restrict__ negative,
    const float*  __restrict__ W,
    float* __restrict__ out,
    int B)
{
    __shared__ float expw[FEAT];
    __shared__ float block_sum;

    for (int i = threadIdx.x; i < FEAT; i += blockDim.x)
        expw[i] = expf(W[i]);
    if (threadIdx.x == 0) block_sum = 0.0f;
    __syncthreads();

    const int lane  = threadIdx.x & 31;
    const int warp  = threadIdx.x >> 5;
    const int wpb   = blockDim.x >> 5;
    const int gwarp = blockIdx.x * wpb + warp;
    const int nwarp = gridDim.x * wpb;

    // Register-resident exp(W): this lane's 3 float4, reused every row.
    float4 wv[3];
    #pragma unroll
    for (int j = 0; j < 3; j++)
        wv[j] = *reinterpret_cast<const float4*>(&expw[(j * 32 + lane) * 4]);

    float acc = 0.0f;   // meaningful on lane 0

    for (int row = gwarp; row < B; row += nwarp) {
        const float4* ar = anchor   + (long long)row * FEAT4;
        const float4* pr = positive + (long long)row * FEAT4;
        const float4* nr = negative + (long long)row * FEAT4;

        // Two independent accumulators halve the serial FMA chain.
        float da = 0.0f, db = 0.0f;
        #pragma unroll
        for (int j = 0; j < 3; j++) {
            const int idx = j * 32 + lane;
            const float4 av = __ldg(&ar[idx]);
            const float4 pv = __ldg(&pr[idx]);
            const float4 nv = __ldg(&nr[idx]);

            float dp, dn;
            dp = av.x - pv.x; dn = av.x - nv.x; da += wv[j].x * (dp * dp - dn * dn);
            dp = av.y - pv.y; dn = av.y - nv.y; db += wv[j].y * (dp * dp - dn * dn);
            dp = av.z - pv.z; dn = av.z - nv.z; da += wv[j].z * (dp * dp - dn * dn);
            dp = av.w - pv.w; dn = av.w - nv.w; db += wv[j].w * (dp * dp - dn * dn);
        }
        float d = da + db;

        #pragma unroll
        for (int off = 16; off > 0; off >>= 1)
            d += __shfl_xor_sync(0xFFFFFFFFu, d, off);

        if (lane == 0)
            acc += fmaxf(d + ALPHA, 0.0f);
    }

    if (lane == 0)
        atomicAdd(&block_sum, acc);
    __syncthreads();

    if (threadIdx.x == 0)
        atomicAdd(out, block_sum * (1.0f / (float)B));
}

extern "C" void kernel_launch(void* const* d_in, const int* in_sizes, int n_in,
                              void* d_out, int out_size) {
    const float4* anchor   = (const float4*)d_in[0];
    const float4* positive = (const float4*)d_in[1];
    const float4* negative = (const float4*)d_in[2];
    const float*  W        = (const float*)d_in[3];
    float* out = (float*)d_out;

    const int B = in_sizes[0] / FEAT;   // 131072

    zero_out_kernel<<<1, 32>>>(out);

    const int threads = 256;
    const int blocks  = 740;            // 148 SMs * 5 resident blocks -> one exact wave
    triplet_kernel<<<blocks, threads>>>(anchor, positive, negative, W, out, B);
}

// round 6
// speedup vs baseline: 1.1220x; 1.0014x over previous
#include <cuda_runtime.h>
#include <cuda_bf16.h>

#define FEAT 384
#define FEAT4 (FEAT / 4)   // 96 float4 per row
#define ALPHA 0.2f

// Cross-block reduction state. Must be zero at the start of every launch;
// the last block restores it to zero, so graph replays are deterministic.
__device__ float        g_sum   = 0.0f;
__device__ unsigned int g_count = 0u;

__global__ __launch_bounds__(256, 5) void triplet_kernel(
    const float4* __restrict__ anchor,
    const float4* __restrict__ positive,
    const float4* __restrict__ negative,
    const float*  __restrict__ W,
    float* __restrict__ out,
    int B)
{
    __shared__ float expw[FEAT];
    __shared__ float block_sum;

    for (int i = threadIdx.x; i < FEAT; i += blockDim.x)
        expw[i] = expf(W[i]);
    if (threadIdx.x == 0) block_sum = 0.0f;
    __syncthreads();

    const int lane  = threadIdx.x & 31;
    const int warp  = threadIdx.x >> 5;
    const int wpb   = blockDim.x >> 5;
    const int gwarp = blockIdx.x * wpb + warp;
    const int nwarp = gridDim.x * wpb;

    // Register-resident exp(W): this lane's 3 float4, reused every row.
    float4 wv[3];
    #pragma unroll
    for (int j = 0; j < 3; j++)
        wv[j] = *reinterpret_cast<const float4*>(&expw[(j * 32 + lane) * 4]);

    float acc = 0.0f;   // meaningful on lane 0

    for (int row = gwarp; row < B; row += nwarp) {
        const float4* ar = anchor   + (long long)row * FEAT4;
        const float4* pr = positive + (long long)row * FEAT4;
        const float4* nr = negative + (long long)row * FEAT4;

        // Two independent accumulators halve the serial FMA chain.
        float da = 0.0f, db = 0.0f;
        #pragma unroll
        for (int j = 0; j < 3; j++) {
            const int idx = j * 32 + lane;
            // Streaming loads: data is read exactly once -> evict-first policy.
            const float4 av = __ldcs(&ar[idx]);
            const float4 pv = __ldcs(&pr[idx]);
            const float4 nv = __ldcs(&nr[idx]);

            float dp, dn;
            dp = av.x - pv.x; dn = av.x - nv.x; da += wv[j].x * (dp * dp - dn * dn);
            dp = av.y - pv.y; dn = av.y - nv.y; db += wv[j].y * (dp * dp - dn * dn);
            dp = av.z - pv.z; dn = av.z - nv.z; da += wv[j].z * (dp * dp - dn * dn);
            dp = av.w - pv.w; dn = av.w - nv.w; db += wv[j].w * (dp * dp - dn * dn);
        }
        float d = da + db;

        #pragma unroll
        for (int off = 16; off > 0; off >>= 1)
            d += __shfl_xor_sync(0xFFFFFFFFu, d, off);

        if (lane == 0)
            acc += fmaxf(d + ALPHA, 0.0f);
    }

    if (lane == 0)
        atomicAdd(&block_sum, acc);
    __syncthreads();

    // Last-block-done: single kernel, no separate zero-init launch.
    if (threadIdx.x == 0) {
        atomicAdd(&g_sum, block_sum);
        __threadfence();
        const unsigned int prev = atomicAdd(&g_count, 1u);
        if (prev == gridDim.x - 1) {
            out[0] = g_sum * (1.0f / (float)B);
            // Restore globals so the next (graph-replayed) launch starts clean.
            g_sum   = 0.0f;
            g_count = 0u;
            __threadfence();
        }
    }
}

extern "C" void kernel_launch(void* const* d_in, const int* in_sizes, int n_in,
                              void* d_out, int out_size) {
    const float4* anchor   = (const float4*)d_in[0];
    const float4* positive = (const float4*)d_in[1];
    const float4* negative = (const float4*)d_in[2];
    const float*  W        = (const float*)d_in[3];
    float* out = (float*)d_out;

    const int B = in_sizes[0] / FEAT;   // 131072

    const int threads = 256;
    const int blocks  = 740;            // 148 SMs * 5 resident blocks -> one exact wave
    triplet_kernel<<<blocks, threads>>>(anchor, positive, negative, W, out, B);
}